// round 8
// baseline (speedup 1.0000x reference)
#include <cuda_runtime.h>

// BatchBlur: per-sample 15x15 depthwise blur with reflect pad.
// x: (32,3,512,512) f32, kernel: (32,15,15) f32, out: (32,3,512,512) f32.
// R6: fma.rn.f32x2 with even/odd dual accumulators (no per-tap shuffles).
//   accE[i] = (o[2i], o[2i+1])   += k[2d]   * E[i+d]
//   accO[s] = (o[2s-1], o[2s])   += k[2d+1] * E[s+d]
//   o[2i]   = accE[i].lo + accO[i].hi ; o[2i+1] = accE[i].hi + accO[i+1].lo

#define BB 32
#define CC 3
#define HH 512
#define WW 512
#define LL 15
#define PP 7

#define TW 128                  // 16 threads x, 8 px each
#define TH 16                   // 8 threads y, 2 rows each
#define IN_ROWS (TH + LL - 1)   // 30
#define CH_ROW 41               // 16B chunks per smem row (odd row shift)
#define ROW_F (CH_ROW * 4)      // 164 floats per smem row
#define LOAD_F 144              // floats loaded per row (need 142)

typedef unsigned long long u64;

__device__ __forceinline__ void ffma2(u64& acc, u64 a, u64 b) {
    asm("fma.rn.f32x2 %0, %1, %2, %0;" : "+l"(acc) : "l"(a), "l"(b));
}
__device__ __forceinline__ float2 u2f(u64 v) {
    float2 f;
    asm("mov.b64 {%0, %1}, %2;" : "=f"(f.x), "=f"(f.y) : "l"(v));
    return f;
}

__device__ __forceinline__ int reflect_idx(int i, int n) {
    i = i < 0 ? -i : i;
    return i >= n ? 2 * n - 2 - i : i;
}

__global__ __launch_bounds__(128, 5) void batchblur_kernel(
    const float* __restrict__ x, const float* __restrict__ ker,
    float* __restrict__ out) {
    __shared__ __align__(16) float s_in[IN_ROWS * ROW_F];
    __shared__ __align__(16) u64 s_kd[LL * 16];  // taps dup'd (k,k), 15+1 pad/row

    const int tid = threadIdx.x;
    const int tx = tid & 15;     // 16 threads across x, 8 px each
    const int tyi = tid >> 4;    // 8 threads across y, 2 rows each

    const int x0 = blockIdx.x * TW;
    const int y0 = blockIdx.y * TH;
    const int img = blockIdx.z;  // b*3 + c
    const int b = img / CC;

    const float* xin = x + (size_t)img * (HH * WW);

    // taps: duplicate into both halves of a u64 for f32x2 broadcast
    for (int i = tid; i < LL * 16; i += 128) {
        int r = i >> 4, c = i & 15;
        float v = (c < 15) ? ker[b * (LL * LL) + r * LL + c] : 0.f;
        float2 d = make_float2(v, v);
        s_kd[i] = *reinterpret_cast<const u64*>(&d);
    }

    // input tile: reflect pad + 16B-chunk XOR swizzle
    for (int idx = tid; idx < IN_ROWS * LOAD_F; idx += 128) {
        int r = idx / LOAD_F;
        int f = idx - r * LOAD_F;
        int gy = reflect_idx(y0 + r - PP, HH);
        int gx = reflect_idx(x0 + f - PP, WW);
        float v = xin[gy * WW + gx];
        int p = f >> 2;
        int q = p ^ ((p >> 3) & 7);
        s_in[r * ROW_F + (q << 2) + (f & 3)] = v;
    }
    __syncthreads();

    // swizzled float offsets of this thread's 6 window chunks
    int woff[6];
#pragma unroll
    for (int j = 0; j < 6; j++) {
        int c = 2 * tx + j;
        woff[j] = (c ^ ((c >> 3) & 7)) << 2;
    }

    u64 w[12];                       // window pairs E[0..11] (use 0..10)
    u64 aEA[4], aEB[4], aOA[5], aOB[5];
#pragma unroll
    for (int i = 0; i < 4; i++) { aEA[i] = 0ull; aEB[i] = 0ull; }
#pragma unroll
    for (int i = 0; i < 5; i++) { aOA[i] = 0ull; aOB[i] = 0ull; }

    const float* rowbase = s_in + (size_t)(2 * tyi) * ROW_F;

#define LOADW(r)                                                              \
    {                                                                         \
        const float* rp_ = rowbase + (r) * ROW_F;                             \
        _Pragma("unroll") for (int j = 0; j < 6; j++) {                       \
            ulonglong2 v_ = *reinterpret_cast<const ulonglong2*>(rp_ + woff[j]); \
            w[2 * j] = v_.x; w[2 * j + 1] = v_.y;                             \
        }                                                                     \
    }

    // one input row feeding out-row A with tap row ka and/or B with kb
#define STEP(DA, DB, kaP, kbP)                                                \
    {                                                                         \
        _Pragma("unroll") for (int j = 0; j < 8; j++) {                       \
            ulonglong2 a2, b2;                                                \
            if (DA) a2 = (kaP)[j];                                            \
            if (DB) b2 = (kbP)[j];                                            \
            _Pragma("unroll") for (int i = 0; i < 4; i++) {                   \
                if (DA) ffma2(aEA[i], w[i + j], a2.x);                        \
                if (DB) ffma2(aEB[i], w[i + j], b2.x);                        \
            }                                                                 \
            if (j < 7) {                                                      \
                _Pragma("unroll") for (int s = 0; s < 5; s++) {               \
                    if (DA) ffma2(aOA[s], w[s + j], a2.y);                    \
                    if (DB) ffma2(aOB[s], w[s + j], b2.y);                    \
                }                                                             \
            }                                                                 \
        }                                                                     \
    }

    const ulonglong2* kbase = reinterpret_cast<const ulonglong2*>(s_kd);

    // r = 0: only out-row A (kernel row 0)
    LOADW(0);
    STEP(true, false, kbase, kbase);

    // r = 1..14: A uses ker[r], B uses ker[r-1]
#pragma unroll 1
    for (int r = 1; r < 15; r++) {
        LOADW(r);
        const ulonglong2* kA = kbase + r * 8;
        const ulonglong2* kB = kA - 8;
        STEP(true, true, kA, kB);
    }

    // r = 15: only out-row B (kernel row 14)
    LOADW(15);
    STEP(false, true, kbase, kbase + 14 * 8);

    // combine parity accumulators and store (16 lanes x 32B contiguous/row)
    float* o = out + (size_t)img * (HH * WW) + (size_t)(y0 + 2 * tyi) * WW +
               x0 + 8 * tx;
    {
        float rA[8], rB[8];
        float2 pA = u2f(aOA[0]), pB = u2f(aOB[0]);
#pragma unroll
        for (int i = 0; i < 4; i++) {
            float2 eA = u2f(aEA[i]), eB = u2f(aEB[i]);
            float2 qA = u2f(aOA[i + 1]), qB = u2f(aOB[i + 1]);
            rA[2 * i] = eA.x + pA.y;
            rA[2 * i + 1] = eA.y + qA.x;
            rB[2 * i] = eB.x + pB.y;
            rB[2 * i + 1] = eB.y + qB.x;
            pA = qA;
            pB = qB;
        }
        *reinterpret_cast<float4*>(o) = make_float4(rA[0], rA[1], rA[2], rA[3]);
        *reinterpret_cast<float4*>(o + 4) = make_float4(rA[4], rA[5], rA[6], rA[7]);
        *reinterpret_cast<float4*>(o + WW) = make_float4(rB[0], rB[1], rB[2], rB[3]);
        *reinterpret_cast<float4*>(o + WW + 4) = make_float4(rB[4], rB[5], rB[6], rB[7]);
    }
}

extern "C" void kernel_launch(void* const* d_in, const int* in_sizes, int n_in,
                              void* d_out, int out_size) {
    const float* x = (const float*)d_in[0];
    const float* k = (const float*)d_in[1];
    float* out = (float*)d_out;
    dim3 grid(WW / TW, HH / TH, BB * CC);
    batchblur_kernel<<<grid, 128>>>(x, k, out);
}

// round 9
// speedup vs baseline: 1.1184x; 1.1184x over previous
#include <cuda_runtime.h>

// BatchBlur: per-sample 15x15 depthwise blur with reflect pad.
// x: (32,3,512,512) f32, kernel: (32,15,15) f32, out: (32,3,512,512) f32.
// R7: scalar FFMA; paired-tap smem rows (k[r-1],k[r]) -> no persistent tap
// arrays, live set ~65 regs, 6 CTAs/SM, high issue with 90% FFMA density.

#define BB 32
#define CC 3
#define HH 512
#define WW 512
#define LL 15
#define PP 7

#define TW 128                  // 16 threads x, 8 px each
#define TH 16                   // 8 threads y, 2 rows each
#define IN_ROWS (TH + LL - 1)   // 30
#define CH_ROW 41               // 16B chunks per smem row (odd -> row shift)
#define ROW_F (CH_ROW * 4)      // 164 floats per smem row
#define LOAD_F 144              // floats loaded per row (need 142)

__device__ __forceinline__ int reflect_idx(int i, int n) {
    i = i < 0 ? -i : i;
    return i >= n ? 2 * n - 2 - i : i;
}

__global__ __launch_bounds__(128, 6) void batchblur_kernel(
    const float* __restrict__ x, const float* __restrict__ ker,
    float* __restrict__ out) {
    __shared__ __align__(16) float s_in[IN_ROWS * ROW_F];
    // s_kp[r][dx] = (k[r-1][dx], k[r][dx]); rows padded to 16 float2
    __shared__ __align__(16) float2 s_kp[16 * 16];

    const int tid = threadIdx.x;
    const int tx = tid & 15;     // 16 threads across x, 8 px each
    const int tyi = tid >> 4;    // 8 threads across y, 2 rows each

    const int x0 = blockIdx.x * TW;
    const int y0 = blockIdx.y * TH;
    const int img = blockIdx.z;  // b*3 + c
    const int b = img / CC;

    const float* xin = x + (size_t)img * (HH * WW);

    // paired taps: row r holds (k[r-1][dx], k[r][dx]); r=0 lo=0, r=15 hi=0
    for (int i = tid; i < 16 * 16; i += 128) {
        int r = i >> 4, dx = i & 15;
        float lo = 0.f, hi = 0.f;
        if (dx < 15) {
            if (r >= 1) lo = ker[b * (LL * LL) + (r - 1) * LL + dx];
            if (r < 15) hi = ker[b * (LL * LL) + r * LL + dx];
        }
        s_kp[i] = make_float2(lo, hi);
    }

    // input tile: reflect pad + 16B-chunk XOR swizzle
    for (int idx = tid; idx < IN_ROWS * LOAD_F; idx += 128) {
        int r = idx / LOAD_F;
        int f = idx - r * LOAD_F;
        int gy = reflect_idx(y0 + r - PP, HH);
        int gx = reflect_idx(x0 + f - PP, WW);
        float v = xin[gy * WW + gx];
        int p = f >> 2;
        int q = p ^ ((p >> 3) & 7);
        s_in[r * ROW_F + (q << 2) + (f & 3)] = v;
    }
    __syncthreads();

    // swizzled float offsets of this thread's 6 window chunks
    int woff[6];
#pragma unroll
    for (int j = 0; j < 6; j++) {
        int c = 2 * tx + j;
        woff[j] = (c ^ ((c >> 3) & 7)) << 2;
    }

    float w[24], accA[8], accB[8];
#pragma unroll
    for (int i = 0; i < 8; i++) { accA[i] = 0.f; accB[i] = 0.f; }

    const float* rowbase = s_in + (size_t)(2 * tyi) * ROW_F;

#define LOADW(r)                                                          \
    {                                                                     \
        const float* rp_ = rowbase + (r) * ROW_F;                         \
        _Pragma("unroll") for (int j = 0; j < 6; j++) {                   \
            float4 v_ = *reinterpret_cast<const float4*>(rp_ + woff[j]);  \
            w[4 * j + 0] = v_.x; w[4 * j + 1] = v_.y;                     \
            w[4 * j + 2] = v_.z; w[4 * j + 3] = v_.w;                     \
        }                                                                 \
    }

    // ---- r = 0: only out-row A (kernel row 0 = .y of s_kp row 0) ----
    LOADW(0);
#pragma unroll
    for (int dx = 0; dx < 15; dx++) {
        float t = s_kp[dx].y;
#pragma unroll
        for (int i = 0; i < 8; i++) accA[i] = fmaf(w[dx + i], t, accA[i]);
    }

    // ---- r = 1..14: accA uses k[r] (.y), accB uses k[r-1] (.x) ----
#pragma unroll 1
    for (int r = 1; r < 15; r++) {
        LOADW(r);
        const float2* kt = s_kp + (r << 4);
#pragma unroll
        for (int dx = 0; dx < 15; dx++) {
            float2 t = kt[dx];
#pragma unroll
            for (int i = 0; i < 8; i++) {
                accA[i] = fmaf(w[dx + i], t.y, accA[i]);
                accB[i] = fmaf(w[dx + i], t.x, accB[i]);
            }
        }
    }

    // ---- r = 15: only out-row B (kernel row 14 = .x of s_kp row 15) ----
    LOADW(15);
#pragma unroll
    for (int dx = 0; dx < 15; dx++) {
        float t = s_kp[(15 << 4) + dx].x;
#pragma unroll
        for (int i = 0; i < 8; i++) accB[i] = fmaf(w[dx + i], t, accB[i]);
    }

    // direct coalesced stores: 16 lanes x 32B = contiguous 512B per row
    float* o = out + (size_t)img * (HH * WW) + (size_t)(y0 + 2 * tyi) * WW +
               x0 + 8 * tx;
    *reinterpret_cast<float4*>(o) = make_float4(accA[0], accA[1], accA[2], accA[3]);
    *reinterpret_cast<float4*>(o + 4) = make_float4(accA[4], accA[5], accA[6], accA[7]);
    *reinterpret_cast<float4*>(o + WW) = make_float4(accB[0], accB[1], accB[2], accB[3]);
    *reinterpret_cast<float4*>(o + WW + 4) = make_float4(accB[4], accB[5], accB[6], accB[7]);
}

extern "C" void kernel_launch(void* const* d_in, const int* in_sizes, int n_in,
                              void* d_out, int out_size) {
    const float* x = (const float*)d_in[0];
    const float* k = (const float*)d_in[1];
    float* out = (float*)d_out;
    dim3 grid(WW / TW, HH / TH, BB * CC);
    batchblur_kernel<<<grid, 128>>>(x, k, out);
}

// round 10
// speedup vs baseline: 1.1832x; 1.0579x over previous
#include <cuda_runtime.h>

// BatchBlur: per-sample 15x15 depthwise blur with reflect pad.
// x: (32,3,512,512) f32, kernel: (32,15,15) f32, out: (32,3,512,512) f32.
// R8: scalar FFMA, 8px x 4 rows per thread (480 FMA per window load),
// quad-packed tap rows, vectorized aligned tile load (left pad 8).

#define BB 32
#define CC 3
#define HH 512
#define WW 512
#define LL 15
#define PP 7

#define TW 128                  // 16 threads x, 8 px each
#define TH 32                   // 8 threads y, 4 rows each
#define IN_ROWS (TH + LL - 1)   // 46
#define CH_ROW 41               // 16B chunks per smem row (odd -> row shift)
#define ROW_F (CH_ROW * 4)      // 164 floats per smem row
#define NCH 36                  // loaded chunks per row: f = 0..143 (need <=142)
#define NSTEP 18                // input rows per thread (4 out rows + 14)

__device__ __forceinline__ int reflect_idx(int i, int n) {
    i = i < 0 ? -i : i;
    return i >= n ? 2 * n - 2 - i : i;
}

__global__ __launch_bounds__(128, 5) void batchblur_kernel(
    const float* __restrict__ x, const float* __restrict__ ker,
    float* __restrict__ out) {
    __shared__ __align__(16) float s_in[IN_ROWS * ROW_F];
    // s_kq[s][dx] = (k[s], k[s-1], k[s-2], k[s-3]) (zero when out of range)
    __shared__ __align__(16) float4 s_kq[NSTEP * 16];

    const int tid = threadIdx.x;
    const int tx = tid & 15;     // 16 threads across x, 8 px each
    const int tyi = tid >> 4;    // 8 threads across y, 4 rows each

    const int x0 = blockIdx.x * TW;
    const int y0 = blockIdx.y * TH;
    const int img = blockIdx.z;  // b*3 + c
    const int b = img / CC;

    const float* xin = x + (size_t)img * (HH * WW);
    const float* kb = ker + b * (LL * LL);

    // quad-packed taps
    for (int i = tid; i < NSTEP * 16; i += 128) {
        int s = i >> 4, dx = i & 15;
        float4 t = make_float4(0.f, 0.f, 0.f, 0.f);
        if (dx < 15) {
            if (s <= 14) t.x = kb[s * LL + dx];
            if (s >= 1 && s <= 15) t.y = kb[(s - 1) * LL + dx];
            if (s >= 2 && s <= 16) t.z = kb[(s - 2) * LL + dx];
            if (s >= 3) t.w = kb[(s - 3) * LL + dx];
        }
        s_kq[i] = t;
    }

    // tile load, vector path: tile float f covers gx = x0-8+f, f=0..143
    {
        const int cLo = (blockIdx.x == 0) ? 2 : 0;
        const int cHi = (blockIdx.x == gridDim.x - 1) ? 33 : 35;
        for (int idx = tid; idx < IN_ROWS * NCH; idx += 128) {
            int r = idx / NCH;
            int c = idx - r * NCH;
            if (c >= cLo && c <= cHi) {
                int gy = reflect_idx(y0 + r - PP, HH);
                float4 v = *reinterpret_cast<const float4*>(
                    xin + (size_t)gy * WW + (x0 - 8 + 4 * c));
                int q = c ^ ((c >> 3) & 7);
                *reinterpret_cast<float4*>(s_in + r * ROW_F + (q << 2)) = v;
            }
        }
        // scalar edges (reflect in x)
        if (blockIdx.x == 0) {
            for (int idx = tid; idx < IN_ROWS * 8; idx += 128) {
                int r = idx >> 3, f = idx & 7;        // f = 0..7, c = 0..1, q = c
                int gy = reflect_idx(y0 + r - PP, HH);
                s_in[r * ROW_F + f] = xin[(size_t)gy * WW + (8 - f)];
            }
        } else if (blockIdx.x == gridDim.x - 1) {
            for (int idx = tid; idx < IN_ROWS * 8; idx += 128) {
                int r = idx >> 3, f = 136 + (idx & 7);  // f = 136..143, c = 34..35
                int gy = reflect_idx(y0 + r - PP, HH);
                int c = f >> 2;
                int q = c ^ 4;                          // 34->38, 35->39
                int gx = 2 * WW - 2 - (x0 - 8 + f);     // reflect
                s_in[r * ROW_F + (q << 2) + (f & 3)] = xin[(size_t)gy * WW + gx];
            }
        }
    }
    __syncthreads();

    // swizzled float offsets of this thread's 6 window chunks
    int woff[6];
#pragma unroll
    for (int j = 0; j < 6; j++) {
        int c = 2 * tx + j;
        woff[j] = (c ^ ((c >> 3) & 7)) << 2;
    }

    float w[24];
    float aA[8], aB[8], aC[8], aD[8];
#pragma unroll
    for (int i = 0; i < 8; i++) { aA[i] = 0.f; aB[i] = 0.f; aC[i] = 0.f; aD[i] = 0.f; }

    const float* rowbase = s_in + (size_t)(4 * tyi) * ROW_F;

#define LOADW(s)                                                          \
    {                                                                     \
        const float* rp_ = rowbase + (s) * ROW_F;                         \
        _Pragma("unroll") for (int j = 0; j < 6; j++) {                   \
            float4 v_ = *reinterpret_cast<const float4*>(rp_ + woff[j]);  \
            w[4 * j + 0] = v_.x; w[4 * j + 1] = v_.y;                     \
            w[4 * j + 2] = v_.z; w[4 * j + 3] = v_.w;                     \
        }                                                                 \
    }

    // out px p uses w[1 + dx + p] (tile has left pad 8, window starts at 8*tx)
#define STEP(s, DA, DB, DC, DD)                                           \
    {                                                                     \
        LOADW(s);                                                         \
        const float4* kq_ = s_kq + ((s) << 4);                            \
        _Pragma("unroll") for (int dx = 0; dx < 15; dx++) {               \
            float4 t_ = kq_[dx];                                          \
            _Pragma("unroll") for (int p = 0; p < 8; p++) {               \
                if (DA) aA[p] = fmaf(w[1 + dx + p], t_.x, aA[p]);         \
                if (DB) aB[p] = fmaf(w[1 + dx + p], t_.y, aB[p]);         \
                if (DC) aC[p] = fmaf(w[1 + dx + p], t_.z, aC[p]);         \
                if (DD) aD[p] = fmaf(w[1 + dx + p], t_.w, aD[p]);         \
            }                                                             \
        }                                                                 \
    }

    STEP(0, true, false, false, false);
    STEP(1, true, true, false, false);
    STEP(2, true, true, true, false);
#pragma unroll 1
    for (int s = 3; s <= 14; s++) {
        STEP(s, true, true, true, true);
    }
    STEP(15, false, true, true, true);
    STEP(16, false, false, true, true);
    STEP(17, false, false, false, true);

    // stores: 16 lanes x 32B contiguous per row, 4 rows
    float* o = out + (size_t)img * (HH * WW) + (size_t)(y0 + 4 * tyi) * WW +
               x0 + 8 * tx;
    *reinterpret_cast<float4*>(o)          = make_float4(aA[0], aA[1], aA[2], aA[3]);
    *reinterpret_cast<float4*>(o + 4)      = make_float4(aA[4], aA[5], aA[6], aA[7]);
    *reinterpret_cast<float4*>(o + WW)     = make_float4(aB[0], aB[1], aB[2], aB[3]);
    *reinterpret_cast<float4*>(o + WW + 4) = make_float4(aB[4], aB[5], aB[6], aB[7]);
    *reinterpret_cast<float4*>(o + 2 * WW)     = make_float4(aC[0], aC[1], aC[2], aC[3]);
    *reinterpret_cast<float4*>(o + 2 * WW + 4) = make_float4(aC[4], aC[5], aC[6], aC[7]);
    *reinterpret_cast<float4*>(o + 3 * WW)     = make_float4(aD[0], aD[1], aD[2], aD[3]);
    *reinterpret_cast<float4*>(o + 3 * WW + 4) = make_float4(aD[4], aD[5], aD[6], aD[7]);
}

extern "C" void kernel_launch(void* const* d_in, const int* in_sizes, int n_in,
                              void* d_out, int out_size) {
    const float* x = (const float*)d_in[0];
    const float* k = (const float*)d_in[1];
    float* out = (float*)d_out;
    dim3 grid(WW / TW, HH / TH, BB * CC);
    batchblur_kernel<<<grid, 128>>>(x, k, out);
}

// round 11
// speedup vs baseline: 1.2408x; 1.0487x over previous
#include <cuda_runtime.h>

// BatchBlur: per-sample 15x15 depthwise blur with reflect pad.
// x: (32,3,512,512) f32, kernel: (32,15,15) f32, out: (32,3,512,512) f32.
// R8: scalar FFMA, 8px x 4 rows per thread (480 FMA per window load),
// quad-packed tap rows, vectorized aligned tile load (left pad 8).

#define BB 32
#define CC 3
#define HH 512
#define WW 512
#define LL 15
#define PP 7

#define TW 128                  // 16 threads x, 8 px each
#define TH 32                   // 8 threads y, 4 rows each
#define IN_ROWS (TH + LL - 1)   // 46
#define CH_ROW 41               // 16B chunks per smem row (odd -> row shift)
#define ROW_F (CH_ROW * 4)      // 164 floats per smem row
#define NCH 36                  // loaded chunks per row: f = 0..143 (need <=142)
#define NSTEP 18                // input rows per thread (4 out rows + 14)

__device__ __forceinline__ int reflect_idx(int i, int n) {
    i = i < 0 ? -i : i;
    return i >= n ? 2 * n - 2 - i : i;
}

__global__ __launch_bounds__(128, 5) void batchblur_kernel(
    const float* __restrict__ x, const float* __restrict__ ker,
    float* __restrict__ out) {
    __shared__ __align__(16) float s_in[IN_ROWS * ROW_F];
    // s_kq[s][dx] = (k[s], k[s-1], k[s-2], k[s-3]) (zero when out of range)
    __shared__ __align__(16) float4 s_kq[NSTEP * 16];

    const int tid = threadIdx.x;
    const int tx = tid & 15;     // 16 threads across x, 8 px each
    const int tyi = tid >> 4;    // 8 threads across y, 4 rows each

    const int x0 = blockIdx.x * TW;
    const int y0 = blockIdx.y * TH;
    const int img = blockIdx.z;  // b*3 + c
    const int b = img / CC;

    const float* xin = x + (size_t)img * (HH * WW);
    const float* kb = ker + b * (LL * LL);

    // quad-packed taps
    for (int i = tid; i < NSTEP * 16; i += 128) {
        int s = i >> 4, dx = i & 15;
        float4 t = make_float4(0.f, 0.f, 0.f, 0.f);
        if (dx < 15) {
            if (s <= 14) t.x = kb[s * LL + dx];
            if (s >= 1 && s <= 15) t.y = kb[(s - 1) * LL + dx];
            if (s >= 2 && s <= 16) t.z = kb[(s - 2) * LL + dx];
            if (s >= 3) t.w = kb[(s - 3) * LL + dx];
        }
        s_kq[i] = t;
    }

    // tile load, vector path: tile float f covers gx = x0-8+f, f=0..143
    {
        const int cLo = (blockIdx.x == 0) ? 2 : 0;
        const int cHi = (blockIdx.x == gridDim.x - 1) ? 33 : 35;
        for (int idx = tid; idx < IN_ROWS * NCH; idx += 128) {
            int r = idx / NCH;
            int c = idx - r * NCH;
            if (c >= cLo && c <= cHi) {
                int gy = reflect_idx(y0 + r - PP, HH);
                float4 v = *reinterpret_cast<const float4*>(
                    xin + (size_t)gy * WW + (x0 - 8 + 4 * c));
                int q = c ^ ((c >> 3) & 7);
                *reinterpret_cast<float4*>(s_in + r * ROW_F + (q << 2)) = v;
            }
        }
        // scalar edges (reflect in x)
        if (blockIdx.x == 0) {
            for (int idx = tid; idx < IN_ROWS * 8; idx += 128) {
                int r = idx >> 3, f = idx & 7;        // f = 0..7, c = 0..1, q = c
                int gy = reflect_idx(y0 + r - PP, HH);
                s_in[r * ROW_F + f] = xin[(size_t)gy * WW + (8 - f)];
            }
        } else if (blockIdx.x == gridDim.x - 1) {
            for (int idx = tid; idx < IN_ROWS * 8; idx += 128) {
                int r = idx >> 3, f = 136 + (idx & 7);  // f = 136..143, c = 34..35
                int gy = reflect_idx(y0 + r - PP, HH);
                int c = f >> 2;
                int q = c ^ 4;                          // 34->38, 35->39
                int gx = 2 * WW - 2 - (x0 - 8 + f);     // reflect
                s_in[r * ROW_F + (q << 2) + (f & 3)] = xin[(size_t)gy * WW + gx];
            }
        }
    }
    __syncthreads();

    // swizzled float offsets of this thread's 6 window chunks
    int woff[6];
#pragma unroll
    for (int j = 0; j < 6; j++) {
        int c = 2 * tx + j;
        woff[j] = (c ^ ((c >> 3) & 7)) << 2;
    }

    float w[24];
    float aA[8], aB[8], aC[8], aD[8];
#pragma unroll
    for (int i = 0; i < 8; i++) { aA[i] = 0.f; aB[i] = 0.f; aC[i] = 0.f; aD[i] = 0.f; }

    const float* rowbase = s_in + (size_t)(4 * tyi) * ROW_F;

#define LOADW(s)                                                          \
    {                                                                     \
        const float* rp_ = rowbase + (s) * ROW_F;                         \
        _Pragma("unroll") for (int j = 0; j < 6; j++) {                   \
            float4 v_ = *reinterpret_cast<const float4*>(rp_ + woff[j]);  \
            w[4 * j + 0] = v_.x; w[4 * j + 1] = v_.y;                     \
            w[4 * j + 2] = v_.z; w[4 * j + 3] = v_.w;                     \
        }                                                                 \
    }

    // out px p uses w[1 + dx + p] (tile has left pad 8, window starts at 8*tx)
#define STEP(s, DA, DB, DC, DD)                                           \
    {                                                                     \
        LOADW(s);                                                         \
        const float4* kq_ = s_kq + ((s) << 4);                            \
        _Pragma("unroll") for (int dx = 0; dx < 15; dx++) {               \
            float4 t_ = kq_[dx];                                          \
            _Pragma("unroll") for (int p = 0; p < 8; p++) {               \
                if (DA) aA[p] = fmaf(w[1 + dx + p], t_.x, aA[p]);         \
                if (DB) aB[p] = fmaf(w[1 + dx + p], t_.y, aB[p]);         \
                if (DC) aC[p] = fmaf(w[1 + dx + p], t_.z, aC[p]);         \
                if (DD) aD[p] = fmaf(w[1 + dx + p], t_.w, aD[p]);         \
            }                                                             \
        }                                                                 \
    }

    STEP(0, true, false, false, false);
    STEP(1, true, true, false, false);
    STEP(2, true, true, true, false);
#pragma unroll 1
    for (int s = 3; s <= 14; s++) {
        STEP(s, true, true, true, true);
    }
    STEP(15, false, true, true, true);
    STEP(16, false, false, true, true);
    STEP(17, false, false, false, true);

    // stores: 16 lanes x 32B contiguous per row, 4 rows
    float* o = out + (size_t)img * (HH * WW) + (size_t)(y0 + 4 * tyi) * WW +
               x0 + 8 * tx;
    *reinterpret_cast<float4*>(o)          = make_float4(aA[0], aA[1], aA[2], aA[3]);
    *reinterpret_cast<float4*>(o + 4)      = make_float4(aA[4], aA[5], aA[6], aA[7]);
    *reinterpret_cast<float4*>(o + WW)     = make_float4(aB[0], aB[1], aB[2], aB[3]);
    *reinterpret_cast<float4*>(o + WW + 4) = make_float4(aB[4], aB[5], aB[6], aB[7]);
    *reinterpret_cast<float4*>(o + 2 * WW)     = make_float4(aC[0], aC[1], aC[2], aC[3]);
    *reinterpret_cast<float4*>(o + 2 * WW + 4) = make_float4(aC[4], aC[5], aC[6], aC[7]);
    *reinterpret_cast<float4*>(o + 3 * WW)     = make_float4(aD[0], aD[1], aD[2], aD[3]);
    *reinterpret_cast<float4*>(o + 3 * WW + 4) = make_float4(aD[4], aD[5], aD[6], aD[7]);
}

extern "C" void kernel_launch(void* const* d_in, const int* in_sizes, int n_in,
                              void* d_out, int out_size) {
    const float* x = (const float*)d_in[0];
    const float* k = (const float*)d_in[1];
    float* out = (float*)d_out;
    dim3 grid(WW / TW, HH / TH, BB * CC);
    batchblur_kernel<<<grid, 128>>>(x, k, out);
}

// round 12
// speedup vs baseline: 1.2429x; 1.0017x over previous
#include <cuda_runtime.h>

// BatchBlur: per-sample 15x15 depthwise blur with reflect pad.
// x: (32,3,512,512) f32, kernel: (32,15,15) f32, out: (32,3,512,512) f32.
// R8: scalar FFMA, 8px x 4 rows per thread (480 FMA per window load),
// quad-packed tap rows, vectorized aligned tile load (left pad 8).

#define BB 32
#define CC 3
#define HH 512
#define WW 512
#define LL 15
#define PP 7

#define TW 128                  // 16 threads x, 8 px each
#define TH 32                   // 8 threads y, 4 rows each
#define IN_ROWS (TH + LL - 1)   // 46
#define CH_ROW 41               // 16B chunks per smem row (odd -> row shift)
#define ROW_F (CH_ROW * 4)      // 164 floats per smem row
#define NCH 36                  // loaded chunks per row: f = 0..143 (need <=142)
#define NSTEP 18                // input rows per thread (4 out rows + 14)

__device__ __forceinline__ int reflect_idx(int i, int n) {
    i = i < 0 ? -i : i;
    return i >= n ? 2 * n - 2 - i : i;
}

__global__ __launch_bounds__(128, 5) void batchblur_kernel(
    const float* __restrict__ x, const float* __restrict__ ker,
    float* __restrict__ out) {
    __shared__ __align__(16) float s_in[IN_ROWS * ROW_F];
    // s_kq[s][dx] = (k[s], k[s-1], k[s-2], k[s-3]) (zero when out of range)
    __shared__ __align__(16) float4 s_kq[NSTEP * 16];

    const int tid = threadIdx.x;
    const int tx = tid & 15;     // 16 threads across x, 8 px each
    const int tyi = tid >> 4;    // 8 threads across y, 4 rows each

    const int x0 = blockIdx.x * TW;
    const int y0 = blockIdx.y * TH;
    const int img = blockIdx.z;  // b*3 + c
    const int b = img / CC;

    const float* xin = x + (size_t)img * (HH * WW);
    const float* kb = ker + b * (LL * LL);

    // quad-packed taps
    for (int i = tid; i < NSTEP * 16; i += 128) {
        int s = i >> 4, dx = i & 15;
        float4 t = make_float4(0.f, 0.f, 0.f, 0.f);
        if (dx < 15) {
            if (s <= 14) t.x = kb[s * LL + dx];
            if (s >= 1 && s <= 15) t.y = kb[(s - 1) * LL + dx];
            if (s >= 2 && s <= 16) t.z = kb[(s - 2) * LL + dx];
            if (s >= 3) t.w = kb[(s - 3) * LL + dx];
        }
        s_kq[i] = t;
    }

    // tile load, vector path: tile float f covers gx = x0-8+f, f=0..143
    {
        const int cLo = (blockIdx.x == 0) ? 2 : 0;
        const int cHi = (blockIdx.x == gridDim.x - 1) ? 33 : 35;
        for (int idx = tid; idx < IN_ROWS * NCH; idx += 128) {
            int r = idx / NCH;
            int c = idx - r * NCH;
            if (c >= cLo && c <= cHi) {
                int gy = reflect_idx(y0 + r - PP, HH);
                float4 v = *reinterpret_cast<const float4*>(
                    xin + (size_t)gy * WW + (x0 - 8 + 4 * c));
                int q = c ^ ((c >> 3) & 7);
                *reinterpret_cast<float4*>(s_in + r * ROW_F + (q << 2)) = v;
            }
        }
        // scalar edges (reflect in x)
        if (blockIdx.x == 0) {
            for (int idx = tid; idx < IN_ROWS * 8; idx += 128) {
                int r = idx >> 3, f = idx & 7;        // f = 0..7, c = 0..1, q = c
                int gy = reflect_idx(y0 + r - PP, HH);
                s_in[r * ROW_F + f] = xin[(size_t)gy * WW + (8 - f)];
            }
        } else if (blockIdx.x == gridDim.x - 1) {
            for (int idx = tid; idx < IN_ROWS * 8; idx += 128) {
                int r = idx >> 3, f = 136 + (idx & 7);  // f = 136..143, c = 34..35
                int gy = reflect_idx(y0 + r - PP, HH);
                int c = f >> 2;
                int q = c ^ 4;                          // 34->38, 35->39
                int gx = 2 * WW - 2 - (x0 - 8 + f);     // reflect
                s_in[r * ROW_F + (q << 2) + (f & 3)] = xin[(size_t)gy * WW + gx];
            }
        }
    }
    __syncthreads();

    // swizzled float offsets of this thread's 6 window chunks
    int woff[6];
#pragma unroll
    for (int j = 0; j < 6; j++) {
        int c = 2 * tx + j;
        woff[j] = (c ^ ((c >> 3) & 7)) << 2;
    }

    float w[24];
    float aA[8], aB[8], aC[8], aD[8];
#pragma unroll
    for (int i = 0; i < 8; i++) { aA[i] = 0.f; aB[i] = 0.f; aC[i] = 0.f; aD[i] = 0.f; }

    const float* rowbase = s_in + (size_t)(4 * tyi) * ROW_F;

#define LOADW(s)                                                          \
    {                                                                     \
        const float* rp_ = rowbase + (s) * ROW_F;                         \
        _Pragma("unroll") for (int j = 0; j < 6; j++) {                   \
            float4 v_ = *reinterpret_cast<const float4*>(rp_ + woff[j]);  \
            w[4 * j + 0] = v_.x; w[4 * j + 1] = v_.y;                     \
            w[4 * j + 2] = v_.z; w[4 * j + 3] = v_.w;                     \
        }                                                                 \
    }

    // out px p uses w[1 + dx + p] (tile has left pad 8, window starts at 8*tx)
#define STEP(s, DA, DB, DC, DD)                                           \
    {                                                                     \
        LOADW(s);                                                         \
        const float4* kq_ = s_kq + ((s) << 4);                            \
        _Pragma("unroll") for (int dx = 0; dx < 15; dx++) {               \
            float4 t_ = kq_[dx];                                          \
            _Pragma("unroll") for (int p = 0; p < 8; p++) {               \
                if (DA) aA[p] = fmaf(w[1 + dx + p], t_.x, aA[p]);         \
                if (DB) aB[p] = fmaf(w[1 + dx + p], t_.y, aB[p]);         \
                if (DC) aC[p] = fmaf(w[1 + dx + p], t_.z, aC[p]);         \
                if (DD) aD[p] = fmaf(w[1 + dx + p], t_.w, aD[p]);         \
            }                                                             \
        }                                                                 \
    }

    STEP(0, true, false, false, false);
    STEP(1, true, true, false, false);
    STEP(2, true, true, true, false);
#pragma unroll 1
    for (int s = 3; s <= 14; s++) {
        STEP(s, true, true, true, true);
    }
    STEP(15, false, true, true, true);
    STEP(16, false, false, true, true);
    STEP(17, false, false, false, true);

    // stores: 16 lanes x 32B contiguous per row, 4 rows
    float* o = out + (size_t)img * (HH * WW) + (size_t)(y0 + 4 * tyi) * WW +
               x0 + 8 * tx;
    *reinterpret_cast<float4*>(o)          = make_float4(aA[0], aA[1], aA[2], aA[3]);
    *reinterpret_cast<float4*>(o + 4)      = make_float4(aA[4], aA[5], aA[6], aA[7]);
    *reinterpret_cast<float4*>(o + WW)     = make_float4(aB[0], aB[1], aB[2], aB[3]);
    *reinterpret_cast<float4*>(o + WW + 4) = make_float4(aB[4], aB[5], aB[6], aB[7]);
    *reinterpret_cast<float4*>(o + 2 * WW)     = make_float4(aC[0], aC[1], aC[2], aC[3]);
    *reinterpret_cast<float4*>(o + 2 * WW + 4) = make_float4(aC[4], aC[5], aC[6], aC[7]);
    *reinterpret_cast<float4*>(o + 3 * WW)     = make_float4(aD[0], aD[1], aD[2], aD[3]);
    *reinterpret_cast<float4*>(o + 3 * WW + 4) = make_float4(aD[4], aD[5], aD[6], aD[7]);
}

extern "C" void kernel_launch(void* const* d_in, const int* in_sizes, int n_in,
                              void* d_out, int out_size) {
    const float* x = (const float*)d_in[0];
    const float* k = (const float*)d_in[1];
    float* out = (float*)d_out;
    dim3 grid(WW / TW, HH / TH, BB * CC);
    batchblur_kernel<<<grid, 128>>>(x, k, out);
}